// round 3
// baseline (speedup 1.0000x reference)
#include <cuda_runtime.h>

#define BATCH    32
#define D_IN     1024
#define D_OUT    1024
#define E_DIM    3076                  // D_OUT + 2*D_IN + 4
#define GROUP    4
#define NGROUPS  (BATCH / GROUP)       // 8
#define NBLOCKS  148
#define NTHREADS 1024
#define NWARPS   (NBLOCKS * (NTHREADS / 32))   // 4736
#define ROWS_G   (GROUP * E_DIM)               // 12304

// Scratch + sync state (allocation-free rule: __device__ globals)
__device__ float    g_out [BATCH * E_DIM];
__device__ float    g_kphi[BATCH * D_IN];
__device__ float    g_qphi[BATCH * D_IN];
__device__ float    g_sig [BATCH * 4];
__device__ unsigned g_flag[NGROUPS];
__device__ unsigned g_count;
__device__ unsigned g_sense;

__global__ void srwm_init()
{
    g_count = 0;
    g_sense = 0;
    for (int i = 0; i < NGROUPS; i++) g_flag[i] = 0;
}

// ---------------------------------------------------------------------------
// Grid barrier: monotonic arrival counter + sense, reset per launch by init.
// ---------------------------------------------------------------------------
__device__ __forceinline__ void grid_barrier(int s)
{
    __threadfence();
    __syncthreads();
    if (threadIdx.x == 0) {
        unsigned target = (unsigned)(s + 1) * NBLOCKS;
        unsigned old = atomicAdd(&g_count, 1u);
        if (old == target - 1u) {
            atomicExch(&g_sense, (unsigned)(s + 1));
        } else {
            while (*(volatile unsigned*)&g_sense < (unsigned)(s + 1))
                __nanosleep(128);
        }
    }
    __syncthreads();
    __threadfence_block();
}

// ---------------------------------------------------------------------------
// Matvec row: g_out[b,e] = w[b,e,:].x[b]; also y for e < D_OUT.
// ---------------------------------------------------------------------------
__device__ __forceinline__ void mv_row(const float* __restrict__ w,
                                       const float* __restrict__ x,
                                       float* __restrict__ y, int write_y,
                                       int b, int e, int lane)
{
    const float4* wrow = (const float4*)(w + ((size_t)b * E_DIM + e) * D_IN);
    const float4* xv4  = (const float4*)(x + (size_t)b * D_IN);
    float acc = 0.f;
#pragma unroll
    for (int j = 0; j < 8; j++) {
        float4 wv = wrow[lane + j * 32];
        float4 xv = __ldg(xv4 + lane + j * 32);
        acc += wv.x * xv.x + wv.y * xv.y + wv.z * xv.z + wv.w * xv.w;
    }
#pragma unroll
    for (int o = 16; o; o >>= 1) acc += __shfl_xor_sync(0xffffffffu, acc, o);
    if (lane == 0) {
        g_out[(size_t)b * E_DIM + e] = acc;
        if (write_y && e < D_OUT) y[(size_t)b * D_OUT + e] = acc;
    }
}

// ---------------------------------------------------------------------------
// Update row: dots vs kphi/qphi, then w_out = w + sig*(v-vbar)*kphi.
// w read __ldcs (last use, expected L2 hit); w_out written __stcs.
// ---------------------------------------------------------------------------
__device__ __forceinline__ void up_row(const float* __restrict__ w,
                                       float* __restrict__ wout,
                                       int b, int e, int lane)
{
    const float4* wrow = (const float4*)(w    + ((size_t)b * E_DIM + e) * D_IN);
    float4*       orow = (float4*)      (wout + ((size_t)b * E_DIM + e) * D_IN);
    const float4* kp = (const float4*)(g_kphi + (size_t)b * D_IN);
    const float4* qp = (const float4*)(g_qphi + (size_t)b * D_IN);

    float4 wv[8];
    float av = 0.f, ab = 0.f;
#pragma unroll
    for (int j = 0; j < 8; j++) {
        wv[j] = __ldcs(wrow + lane + j * 32);
        float4 kv = __ldg(kp + lane + j * 32);
        float4 qv = __ldg(qp + lane + j * 32);
        ab += wv[j].x * kv.x + wv[j].y * kv.y + wv[j].z * kv.z + wv[j].w * kv.w;
        av += wv[j].x * qv.x + wv[j].y * qv.y + wv[j].z * qv.z + wv[j].w * qv.w;
    }
#pragma unroll
    for (int o = 16; o; o >>= 1) {
        av += __shfl_xor_sync(0xffffffffu, av, o);
        ab += __shfl_xor_sync(0xffffffffu, ab, o);
    }
    int seg = (e < D_OUT) ? 0 : (e < D_OUT + D_IN) ? 1 : (e < D_OUT + 2 * D_IN) ? 2 : 3;
    float coeff = __ldg(&g_sig[b * 4 + seg]) * (av - ab);
#pragma unroll
    for (int j = 0; j < 8; j++) {
        float4 kv = __ldg(kp + lane + j * 32);
        float4 o4;
        o4.x = wv[j].x + coeff * kv.x;
        o4.y = wv[j].y + coeff * kv.y;
        o4.z = wv[j].z + coeff * kv.z;
        o4.w = wv[j].w + coeff * kv.w;
        __stcs(orow + lane + j * 32, o4);
    }
}

// ---------------------------------------------------------------------------
// Designated-block softmax: block bid (0..7) handles task bid for group gi:
// batch = gi*GROUP + bid/2, kind = bid&1 (k or q). Block 0 also does sigmoids.
// Ends with fence + flag arrival (waiters wait for 8 arrivals).
// ---------------------------------------------------------------------------
__device__ void softmax_task(int gi, int bid, int tid)
{
    __shared__ float sred[32];
    const int b    = gi * GROUP + (bid >> 1);
    const int lane = tid & 31;
    const int warp = tid >> 5;

    const float* src = g_out + (size_t)b * E_DIM + D_OUT + (size_t)(bid & 1) * D_IN;
    float v = __ldcg(src + tid);

    // block max
    float m = v;
#pragma unroll
    for (int o = 16; o; o >>= 1) m = fmaxf(m, __shfl_xor_sync(0xffffffffu, m, o));
    if (lane == 0) sred[warp] = m;
    __syncthreads();
    if (tid < 32) {
        float t = sred[tid];
#pragma unroll
        for (int o = 16; o; o >>= 1) t = fmaxf(t, __shfl_xor_sync(0xffffffffu, t, o));
        if (tid == 0) sred[0] = t;
    }
    __syncthreads();
    m = sred[0];
    __syncthreads();

    float ev = __expf(v - m);

    // block sum
    float s = ev;
#pragma unroll
    for (int o = 16; o; o >>= 1) s += __shfl_xor_sync(0xffffffffu, s, o);
    if (lane == 0) sred[warp] = s;
    __syncthreads();
    if (tid < 32) {
        float t = sred[tid];
#pragma unroll
        for (int o = 16; o; o >>= 1) t += __shfl_xor_sync(0xffffffffu, t, o);
        if (tid == 0) sred[0] = t;
    }
    __syncthreads();
    float inv = 1.0f / sred[0];

    float* dst = (bid & 1) ? g_qphi : g_kphi;
    dst[(size_t)b * D_IN + tid] = ev * inv;

    if (bid == 0 && tid < 4 * GROUP) {
        int bb = gi * GROUP + (tid >> 2), k = tid & 3;
        float t = __ldcg(&g_out[(size_t)bb * E_DIM + D_OUT + 2 * D_IN + k]);
        g_sig[bb * 4 + k] = 1.0f / (1.0f + __expf(-t));
    }

    __threadfence();
    __syncthreads();
    if (tid == 0) atomicAdd(&g_flag[gi], 1u);
}

// ---------------------------------------------------------------------------
// Persistent kernel: 9 stages; stage s = softmax(s-1) | mv-chunk1(s) |
// flag-wait | update(s-1) | mv-rest(s) | barrier.
// ---------------------------------------------------------------------------
__global__ void __launch_bounds__(NTHREADS, 1)
srwm_main(const float* __restrict__ w, const float* __restrict__ x,
          float* __restrict__ y, float* __restrict__ wout, int write_y)
{
    const int tid  = threadIdx.x;
    const int bid  = blockIdx.x;
    const int wid  = tid >> 5;
    const int lane = tid & 31;
    const int gw   = bid * (NTHREADS / 32) + wid;

    for (int s = 0; s <= NGROUPS; s++) {
        // softmax for previous group by designated blocks (off critical path)
        if (s >= 1 && bid < 8) softmax_task(s - 1, bid, tid);

        // matvec chunk 1 of current group (~38% of rows; covers softmax latency)
        if (s < NGROUPS) {
            int lr = gw;
            if (lr < ROWS_G) {
                int bi = lr / E_DIM;
                mv_row(w, x, y, write_y, s * GROUP + bi, lr - bi * E_DIM, lane);
            }
        }

        // update previous group (after its softmax flag; w in L2 from stage s-1)
        if (s >= 1) {
            __syncthreads();
            if (tid == 0) {
                while (*(volatile unsigned*)&g_flag[s - 1] < 8u) __nanosleep(128);
            }
            __syncthreads();
            const int gi = s - 1;
            for (int lr = gw; lr < ROWS_G; lr += NWARPS) {
                int bi = lr / E_DIM;
                up_row(w, wout, gi * GROUP + bi, lr - bi * E_DIM, lane);
            }
        }

        // remaining matvec rows of current group
        if (s < NGROUPS) {
            for (int lr = gw + NWARPS; lr < ROWS_G; lr += NWARPS) {
                int bi = lr / E_DIM;
                mv_row(w, x, y, write_y, s * GROUP + bi, lr - bi * E_DIM, lane);
            }
            grid_barrier(s);
        }
    }
}

// ---------------------------------------------------------------------------
// kernel_launch: init (reset sync state) + one persistent kernel.
// ---------------------------------------------------------------------------
extern "C" void kernel_launch(void* const* d_in, const int* in_sizes, int n_in,
                              void* d_out, int out_size)
{
    const float* x = (const float*)d_in[0];
    const float* w = (const float*)d_in[1];
    if (n_in >= 2 && in_sizes[0] != BATCH * D_IN) {
        x = (const float*)d_in[1];
        w = (const float*)d_in[0];
    }

    const size_t wout_elems = (size_t)BATCH * E_DIM * D_IN;
    float* out = (float*)d_out;

    float* y_ptr    = out;
    float* wout_ptr = out + ((size_t)out_size - wout_elems);
    const int write_y = ((size_t)out_size > wout_elems) ? 1 : 0;

    srwm_init<<<1, 1>>>();
    srwm_main<<<NBLOCKS, NTHREADS>>>(w, x, y_ptr, wout_ptr, write_y);
}

// round 4
// speedup vs baseline: 1.3454x; 1.3454x over previous
#include <cuda_runtime.h>

#define BATCH    32
#define D_IN     1024
#define D_OUT    1024
#define E_DIM    3076                    // D_OUT + 2*D_IN + 4
#define GROUP    4
#define NGROUPS  (BATCH / GROUP)         // 8
#define ROWS_G   (GROUP * E_DIM)         // 12304
#define MV_BLOCKS (ROWS_G / 8)           // 1538 (8 warps/block, 1 row/warp)
#define UPB_PER_BATCH ((E_DIM + 31) / 32) // 97
#define UP_BLOCKS (UPB_PER_BATCH * GROUP) // 388

// Scratch + sync (allocation-free rule: __device__ globals)
__device__ float    g_out [BATCH * E_DIM];
__device__ float    g_kphi[BATCH * D_IN];
__device__ float    g_qphi[BATCH * D_IN];
__device__ float    g_sig [BATCH * 4];
__device__ unsigned g_flag[NGROUPS];

__global__ void srwm_init()
{
    for (int i = 0; i < NGROUPS; i++) g_flag[i] = 0;
}

// ---------------------------------------------------------------------------
// Softmax task: task in [0,8): batch = gi*GROUP + task/2, kind = task&1.
// 256 threads, 4 elems each (float4). Task 0 also does the 16 sigmoids.
// ---------------------------------------------------------------------------
__device__ void softmax_task(int gi, int task, int tid)
{
    __shared__ float sred[8];
    __shared__ float sval;
    const int b    = gi * GROUP + (task >> 1);
    const int lane = tid & 31;
    const int warp = tid >> 5;

    const float* src = g_out + (size_t)b * E_DIM + D_OUT + (size_t)(task & 1) * D_IN;
    float4 v = ((const float4*)src)[tid];

    float m = fmaxf(fmaxf(v.x, v.y), fmaxf(v.z, v.w));
#pragma unroll
    for (int o = 16; o; o >>= 1) m = fmaxf(m, __shfl_xor_sync(0xffffffffu, m, o));
    if (lane == 0) sred[warp] = m;
    __syncthreads();
    if (tid == 0) {
        float t = sred[0];
#pragma unroll
        for (int i = 1; i < 8; i++) t = fmaxf(t, sred[i]);
        sval = t;
    }
    __syncthreads();
    m = sval;
    float e0 = __expf(v.x - m), e1 = __expf(v.y - m);
    float e2 = __expf(v.z - m), e3 = __expf(v.w - m);
    float s = e0 + e1 + e2 + e3;
#pragma unroll
    for (int o = 16; o; o >>= 1) s += __shfl_xor_sync(0xffffffffu, s, o);
    __syncthreads();
    if (lane == 0) sred[warp] = s;
    __syncthreads();
    if (tid == 0) {
        float t = 0.f;
#pragma unroll
        for (int i = 0; i < 8; i++) t += sred[i];
        sval = t;
    }
    __syncthreads();
    float inv = 1.0f / sval;
    float* dst = (task & 1) ? g_qphi : g_kphi;
    float4 o4 = {e0 * inv, e1 * inv, e2 * inv, e3 * inv};
    ((float4*)(dst + (size_t)b * D_IN))[tid] = o4;

    if (task == 0 && tid < 4 * GROUP) {
        int bb = gi * GROUP + (tid >> 2), k = tid & 3;
        float t = g_out[(size_t)bb * E_DIM + D_OUT + 2 * D_IN + k];
        g_sig[bb * 4 + k] = 1.0f / (1.0f + __expf(-t));
    }

    __threadfence();
    __syncthreads();
    if (tid == 0) atomicAdd(&g_flag[gi], 1u);
}

// ---------------------------------------------------------------------------
// Combined kernel. Block roles by blockIdx.x:
//   g_mv >= 0 : first MV_BLOCKS blocks do matvec rows of group g_mv.
//   g_up >= 0 : remaining UP_BLOCKS blocks do the update of group g_up.
// Blocks 0..7 additionally compute softmax(g_up) first (they are wave-1).
// ---------------------------------------------------------------------------
__global__ void __launch_bounds__(256)
srwm_stage(const float* __restrict__ w, const float* __restrict__ x,
           float* __restrict__ y, float* __restrict__ wout,
           int write_y, int g_mv, int g_up)
{
    const int tid  = threadIdx.x;
    const int bid  = blockIdx.x;
    const int lane = tid & 31;
    const int warp = tid >> 5;
    const int n_mv = (g_mv >= 0) ? MV_BLOCKS : 0;

    // ---- softmax for the update group, by the first 8 blocks ----
    if (g_up >= 0 && bid < 8) {
        softmax_task(g_up, bid, tid);
        __syncthreads();
    }

    if (bid < n_mv) {
        // =============== MATVEC role ===============
        const int row = bid * 8 + warp;            // < ROWS_G (exact)
        const int bi  = row / E_DIM;
        const int e   = row - bi * E_DIM;
        const int b   = g_mv * GROUP + bi;

        const float4* wrow = (const float4*)(w + ((size_t)b * E_DIM + e) * D_IN);
        const float4* x4   = (const float4*)(x + (size_t)b * D_IN);

        float acc = 0.f;
#pragma unroll
        for (int j = 0; j < 8; j++) {
            float4 wv = wrow[lane + j * 32];
            float4 xv = __ldg(x4 + lane + j * 32);
            acc += wv.x * xv.x + wv.y * xv.y + wv.z * xv.z + wv.w * xv.w;
        }
#pragma unroll
        for (int o = 16; o; o >>= 1) acc += __shfl_xor_sync(0xffffffffu, acc, o);
        if (lane == 0) {
            g_out[(size_t)b * E_DIM + e] = acc;
            if (write_y && e < D_OUT) y[(size_t)b * D_OUT + e] = acc;
        }
        return;
    }

    if (g_up < 0) return;

    // =============== UPDATE role ===============
    const int ub = bid - n_mv;                     // 0 .. UP_BLOCKS-1
    const int bi = ub / UPB_PER_BATCH;
    const int b  = g_up * GROUP + bi;
    const int e0 = (ub - bi * UPB_PER_BATCH) * 32;

    __shared__ float4 sk4[D_IN / 4];
    __shared__ float4 sq4[D_IN / 4];
    __shared__ float  ssig[4];

    // wait for softmax(g_up) (flag == 8) — producers are blocks 0..7 (wave 1)
    if (tid == 0) {
        while (*(volatile unsigned*)&g_flag[g_up] < 8u) __nanosleep(64);
    }
    __syncthreads();

    const float4* gk = (const float4*)(g_kphi + (size_t)b * D_IN);
    const float4* gq = (const float4*)(g_qphi + (size_t)b * D_IN);
    for (int i = tid; i < D_IN / 4; i += 256) {
        sk4[i] = gk[i];
        sq4[i] = gq[i];
    }
    if (tid < 4) ssig[tid] = g_sig[b * 4 + tid];
    __syncthreads();

#pragma unroll 1
    for (int r = 0; r < 4; r++) {
        const int e = e0 + warp * 4 + r;
        if (e >= E_DIM) break;

        const float4* wrow = (const float4*)(w    + ((size_t)b * E_DIM + e) * D_IN);
        float4*       orow = (float4*)      (wout + ((size_t)b * E_DIM + e) * D_IN);

        float4 wv[8];
        float av = 0.f, ab = 0.f;
#pragma unroll
        for (int j = 0; j < 8; j++) {
            wv[j] = __ldcs(wrow + lane + j * 32);
            float4 kv = sk4[lane + j * 32];
            float4 qv = sq4[lane + j * 32];
            ab += wv[j].x * kv.x + wv[j].y * kv.y + wv[j].z * kv.z + wv[j].w * kv.w;
            av += wv[j].x * qv.x + wv[j].y * qv.y + wv[j].z * qv.z + wv[j].w * qv.w;
        }
#pragma unroll
        for (int o = 16; o; o >>= 1) {
            av += __shfl_xor_sync(0xffffffffu, av, o);
            ab += __shfl_xor_sync(0xffffffffu, ab, o);
        }
        const int seg = (e < D_OUT) ? 0 : (e < D_OUT + D_IN) ? 1 :
                        (e < D_OUT + 2 * D_IN) ? 2 : 3;
        const float coeff = ssig[seg] * (av - ab);
#pragma unroll
        for (int j = 0; j < 8; j++) {
            float4 kv = sk4[lane + j * 32];
            float4 o4;
            o4.x = wv[j].x + coeff * kv.x;
            o4.y = wv[j].y + coeff * kv.y;
            o4.z = wv[j].z + coeff * kv.z;
            o4.w = wv[j].w + coeff * kv.w;
            __stcs(orow + lane + j * 32, o4);
        }
    }
}

// ---------------------------------------------------------------------------
// kernel_launch: init + 9 pipelined stage kernels (10 graph nodes).
// ---------------------------------------------------------------------------
extern "C" void kernel_launch(void* const* d_in, const int* in_sizes, int n_in,
                              void* d_out, int out_size)
{
    const float* x = (const float*)d_in[0];
    const float* w = (const float*)d_in[1];
    if (n_in >= 2 && in_sizes[0] != BATCH * D_IN) {
        x = (const float*)d_in[1];
        w = (const float*)d_in[0];
    }

    const size_t wout_elems = (size_t)BATCH * E_DIM * D_IN;
    float* out = (float*)d_out;

    float* y_ptr    = out;
    float* wout_ptr = out + ((size_t)out_size - wout_elems);
    const int write_y = ((size_t)out_size > wout_elems) ? 1 : 0;

    srwm_init<<<1, 1>>>();

    // stage 0: matvec only
    srwm_stage<<<MV_BLOCKS, 256>>>(w, x, y_ptr, wout_ptr, write_y, 0, -1);
    // stages 1..7: mv(s) + update(s-1)
    for (int s = 1; s < NGROUPS; s++)
        srwm_stage<<<MV_BLOCKS + UP_BLOCKS, 256>>>(w, x, y_ptr, wout_ptr,
                                                   write_y, s, s - 1);
    // final: update(7) only (blocks 0..7 do softmax(7) first)
    srwm_stage<<<UP_BLOCKS, 256>>>(w, x, y_ptr, wout_ptr, write_y, -1,
                                   NGROUPS - 1);
}